// round 14
// baseline (speedup 1.0000x reference)
#include <cuda_runtime.h>
#include <cuda_fp16.h>

#define NB   8
#define NP   2048
#define C1   64
#define C2   128
#define NS   64
#define RAD2 0.36f

// Scratch
__device__ __half g_fh[NB * NP * C2];          // f[b,n,128] fp16 (4 MB, L2)
__device__ float4 g_xq[NB * NP];               // (x,y,z,|x|^2)
__device__ unsigned short g_nbr[NB * NP * NS]; // padded neighbor lists (2 MB)

// ---------------------------------------------------------------------------
// Kernel 0: pack coords + squared norm
// ---------------------------------------------------------------------------
__global__ __launch_bounds__(256)
void xq_kernel(const float* __restrict__ x)
{
    int p = blockIdx.x * 256 + threadIdx.x;
    if (p >= NB * NP) return;
    float a0 = x[p * 3 + 0];
    float a1 = x[p * 3 + 1];
    float a2 = x[p * 3 + 2];
    g_xq[p] = make_float4(a0, a1, a2, a0 * a0 + a1 * a1 + a2 * a2);
}

// ---------------------------------------------------------------------------
// Kernel 1: ball-query scan. One warp per center; writes a 64-entry neighbor
// list padded with the first neighbor (== reference semantics under max).
// Tiny smem/regs -> near-full occupancy hides the serial scan chain.
// ---------------------------------------------------------------------------
__global__ __launch_bounds__(256)
void scan_kernel(void)
{
    __shared__ unsigned short nbr[8][NS];      // 1 KB

    int tid  = threadIdx.x;
    int warp = tid >> 5, lane = tid & 31;
    int sg   = blockIdx.x * 8 + warp;          // global center id
    int b    = sg >> 11;                       // / NP
    int s    = sg & (NP - 1);

    const float4* xq = g_xq + b * NP;
    float4 c = __ldg(&xq[s]);

    int cnt = 0;
    for (int j0 = 0; j0 < NP && cnt < NS; j0 += 64) {
        int ja = j0 + lane;
        int jb = ja + 32;
        float4 pa = __ldg(&xq[ja]);
        float4 pb = __ldg(&xq[jb]);

        float da = c.w + pa.w - 2.f * (c.x * pa.x + c.y * pa.y + c.z * pa.z);
        bool oka = !(da > RAD2);
        unsigned ma = __ballot_sync(0xffffffffu, oka);
        int ra = __popc(ma & ((1u << lane) - 1u));
        if (oka && (cnt + ra) < NS)
            nbr[warp][cnt + ra] = (unsigned short)ja;
        cnt += __popc(ma);
        if (cnt > NS) cnt = NS;
        if (cnt >= NS) break;

        float db = c.w + pb.w - 2.f * (c.x * pb.x + c.y * pb.y + c.z * pb.z);
        bool okb = !(db > RAD2);
        unsigned mb = __ballot_sync(0xffffffffu, okb);
        int rb = __popc(mb & ((1u << lane) - 1u));
        if (okb && (cnt + rb) < NS)
            nbr[warp][cnt + rb] = (unsigned short)jb;
        cnt += __popc(mb);
        if (cnt > NS) cnt = NS;
    }
    __syncwarp();

    // Pad to 64 with the first neighbor (center always in-radius -> cnt >= 1)
    unsigned short first = nbr[warp][0];
    unsigned short va = (lane      < cnt) ? nbr[warp][lane]      : first;
    unsigned short vb = (lane + 32 < cnt) ? nbr[warp][lane + 32] : first;

    unsigned short* gn = g_nbr + (size_t)sg * NS;
    gn[lane]      = va;
    gn[lane + 32] = vb;
}

// ---------------------------------------------------------------------------
// Kernel 2: per-point MLP (exact R10 winner, untouched).
// ---------------------------------------------------------------------------
__global__ __launch_bounds__(256)
void mlp_kernel(const float* __restrict__ x,
                const float* __restrict__ W1,
                const float* __restrict__ b1,
                const float* __restrict__ W2,
                const float* __restrict__ b2)
{
    __shared__ float w2t[C1][C2];      // 32 KB, [k][p]
    __shared__ float h1s[128][C1];     // 32 KB
    __shared__ float xs3[128 * 3];
    __shared__ float b2s[C2];

    int tid = threadIdx.x;
    int p0  = blockIdx.x * 128;

    for (int i = tid; i < C2 * C1; i += 256) {
        int p = i >> 6, k = i & 63;
        w2t[k][p] = W2[i];
    }
    for (int i = tid; i < 128 * 3; i += 256) xs3[i] = x[p0 * 3 + i];
    if (tid < C2) b2s[tid] = b2[tid];
    __syncthreads();

    for (int i = tid; i < 128 * C1; i += 256) {
        int q = i >> 6, c = i & 63;
        float v = fmaf(W1[c * 3 + 2], xs3[q * 3 + 2],
                  fmaf(W1[c * 3 + 1], xs3[q * 3 + 1],
                  fmaf(W1[c * 3 + 0], xs3[q * 3 + 0], b1[c])));
        h1s[q][c] = fmaxf(v, 0.f);
    }
    __syncthreads();

    int warp = tid >> 5, lane = tid & 31;
    int lane4 = lane * 4;
    float4 binit = *(const float4*)&b2s[lane4];

    for (int pass = 0; pass < 2; pass++) {
        int q0 = warp * 16 + pass * 8;
        float4 acc[8];
        #pragma unroll
        for (int p = 0; p < 8; p++) acc[p] = binit;

        #pragma unroll 2
        for (int k = 0; k < C1; k += 4) {
            float4 w0 = *(const float4*)(w2t[k + 0] + lane4);
            float4 w1 = *(const float4*)(w2t[k + 1] + lane4);
            float4 w2 = *(const float4*)(w2t[k + 2] + lane4);
            float4 w3 = *(const float4*)(w2t[k + 3] + lane4);
            #pragma unroll
            for (int p = 0; p < 8; p++) {
                float4 h = *(const float4*)(h1s[q0 + p] + k);
                float4 a = acc[p];
                a.x = fmaf(h.x, w0.x, a.x); a.y = fmaf(h.x, w0.y, a.y);
                a.z = fmaf(h.x, w0.z, a.z); a.w = fmaf(h.x, w0.w, a.w);
                a.x = fmaf(h.y, w1.x, a.x); a.y = fmaf(h.y, w1.y, a.y);
                a.z = fmaf(h.y, w1.z, a.z); a.w = fmaf(h.y, w1.w, a.w);
                a.x = fmaf(h.z, w2.x, a.x); a.y = fmaf(h.z, w2.y, a.y);
                a.z = fmaf(h.z, w2.z, a.z); a.w = fmaf(h.z, w2.w, a.w);
                a.x = fmaf(h.w, w3.x, a.x); a.y = fmaf(h.w, w3.y, a.y);
                a.z = fmaf(h.w, w3.z, a.z); a.w = fmaf(h.w, w3.w, a.w);
                acc[p] = a;
            }
        }

        #pragma unroll
        for (int p = 0; p < 8; p++) {
            float4 v = acc[p];
            __half2 h01 = __floats2half2_rn(fmaxf(v.x, 0.f), fmaxf(v.y, 0.f));
            __half2 h23 = __floats2half2_rn(fmaxf(v.z, 0.f), fmaxf(v.w, 0.f));
            uint2 st;
            st.x = *(unsigned*)&h01;
            st.y = *(unsigned*)&h23;
            ((uint2*)(g_fh + (size_t)(p0 + q0 + p) * C2))[lane] = st;
        }
    }
}

// ---------------------------------------------------------------------------
// Kernel 3: gather + fp16 max-pool. Branch-free: exactly 8 iterations of 4
// paired LDG.128s per warp (lists pre-padded to 64). Indices via broadcast
// uint4 loads. Epilogue transpose identical to R10.
// ---------------------------------------------------------------------------
__global__ __launch_bounds__(256, 6)
void gather_kernel(float* __restrict__ out)
{
    __shared__ float tr[8][132];

    int b    = blockIdx.y;
    int tid  = threadIdx.x;
    int warp = tid >> 5, lane = tid & 31;
    int half = lane >> 4;
    int lo   = lane & 15;
    int s    = blockIdx.x * 8 + warp;

    const uint4* nl  = (const uint4*)(g_nbr + ((size_t)b * NP + s) * NS); // 8 uint4
    const uint4* fb4 = (const uint4*)(g_fh + (size_t)b * NP * C2);        // 16 uint4/row

    __half2 m0 = __float2half2_rn(0.f);
    __half2 m1 = m0, m2 = m0, m3 = m0;

    #pragma unroll
    for (int it = 0; it < 8; it++) {
        uint4 nw = __ldg(&nl[it]);              // 8 ushort indices (broadcast)
        int j0 = half ? (int)(nw.x >> 16) : (int)(nw.x & 0xffffu);
        int j1 = half ? (int)(nw.y >> 16) : (int)(nw.y & 0xffffu);
        int j2 = half ? (int)(nw.z >> 16) : (int)(nw.z & 0xffffu);
        int j3 = half ? (int)(nw.w >> 16) : (int)(nw.w & 0xffffu);
        uint4 v0 = fb4[j0 * 16 + lo];
        uint4 v1 = fb4[j1 * 16 + lo];
        uint4 v2 = fb4[j2 * 16 + lo];
        uint4 v3 = fb4[j3 * 16 + lo];
        #define HM(v) \
            m0 = __hmax2(m0, *reinterpret_cast<__half2*>(&v.x)); \
            m1 = __hmax2(m1, *reinterpret_cast<__half2*>(&v.y)); \
            m2 = __hmax2(m2, *reinterpret_cast<__half2*>(&v.z)); \
            m3 = __hmax2(m3, *reinterpret_cast<__half2*>(&v.w));
        HM(v0) HM(v1) HM(v2) HM(v3)
        #undef HM
    }

    #define XMAX(m) { unsigned o = __shfl_xor_sync(0xffffffffu, *(unsigned*)&m, 16); \
                      m = __hmax2(m, *reinterpret_cast<__half2*>(&o)); }
    XMAX(m0) XMAX(m1) XMAX(m2) XMAX(m3)
    #undef XMAX

    if (half == 0) {
        float2 f0 = __half22float2(m0);
        float2 f1 = __half22float2(m1);
        float2 f2 = __half22float2(m2);
        float2 f3 = __half22float2(m3);
        float* t = &tr[warp][lo * 8];
        t[0] = f0.x; t[1] = f0.y; t[2] = f1.x; t[3] = f1.y;
        t[4] = f2.x; t[5] = f2.y; t[6] = f3.x; t[7] = f3.y;
    }
    __syncthreads();

    float* ob = out + (size_t)b * C2 * NP + blockIdx.x * 8;
    for (int i = tid; i < C2 * 8; i += 256) {
        int si = i & 7;
        int p  = i >> 3;
        ob[p * NP + si] = tr[si][p];
    }
}

extern "C" void kernel_launch(void* const* d_in, const int* in_sizes, int n_in,
                              void* d_out, int out_size)
{
    const float* x  = (const float*)d_in[0];
    const float* W1 = (const float*)d_in[1];
    const float* b1 = (const float*)d_in[2];
    const float* W2 = (const float*)d_in[3];
    const float* b2 = (const float*)d_in[4];
    float* out = (float*)d_out;

    xq_kernel<<<(NB * NP + 255) / 256, 256>>>(x);
    scan_kernel<<<(NB * NP) / 8, 256>>>();
    mlp_kernel<<<(NB * NP) / 128, 256>>>(x, W1, b1, W2, b2);
    dim3 grid(NP / 8, NB);
    gather_kernel<<<grid, 256>>>(out);
}